// round 8
// baseline (speedup 1.0000x reference)
#include <cuda_runtime.h>
#include <cuda_fp16.h>

// ApproximateConv2d: z[b,o,h,w] = mu_w * sum_{c,kh,kw} min(x_pad, w)
// x: (4,32,56,56) f32, w: (64,32,3,3) f32, out: (4,64,56,56) f32
//
// R8 = R7 (packed fp16 min/add, fp32 chunk accumulators) with TO=4:
// doubles thread count (200K) -> ~42 warps/SM ceiling, issue-rate recovery.

#define Bn 4
#define Cn 32
#define Hn 56
#define Wn 56
#define On 64
#define KK 9
#define CKK 288

#define TO 4              // output channels per thread
#define OG (On / TO)      // 16
#define TH 4              // output rows per block
#define NBAND (Hn / TH)   // 14
#define THREADS (TH * Wn) // 224

#define CCHUNK 16
#define NCHUNK (Cn / CCHUNK) // 2
#define XS_ROWS (TH + 2)     // 6
#define XS_COLS (Wn + 2)     // 58
#define XS_PLANE (XS_ROWS * XS_COLS)
#define XS_SIZE (CCHUNK * XS_PLANE)

__device__ float g_mu;

// ---------------------------------------------------------------------------
// mu_w = mean(|w|) in fp32 (exact)
// ---------------------------------------------------------------------------
__global__ __launch_bounds__(1024)
void mu_kernel(const float* __restrict__ w) {
    __shared__ float red[32];
    const int n4 = (On * CKK) / 4; // 4608
    const float4* w4 = reinterpret_cast<const float4*>(w);
    float s = 0.f;
    for (int i = threadIdx.x; i < n4; i += 1024) {
        float4 v = w4[i];
        s += fabsf(v.x) + fabsf(v.y) + fabsf(v.z) + fabsf(v.w);
    }
#pragma unroll
    for (int off = 16; off > 0; off >>= 1)
        s += __shfl_xor_sync(0xffffffffu, s, off);
    if ((threadIdx.x & 31) == 0) red[threadIdx.x >> 5] = s;
    __syncthreads();
    if (threadIdx.x < 32) {
        float t = red[threadIdx.x];
#pragma unroll
        for (int off = 16; off > 0; off >>= 1)
            t += __shfl_xor_sync(0xffffffffu, t, off);
        if (threadIdx.x == 0) g_mu = t / (float)(On * CKK);
    }
}

// ---------------------------------------------------------------------------
// Main kernel. grid = (OG=16, NBAND=14, Bn=4) = 896 blocks, 224 threads.
// Thread = one output pixel in a 4x56 band, TO=4 output channels.
// Inner math in packed fp16; per-channel (9-term) chunks flushed to fp32.
// ---------------------------------------------------------------------------
__global__ __launch_bounds__(THREADS, 6)
void approx_conv_kernel(const float* __restrict__ x,
                        const float* __restrict__ w,
                        float* __restrict__ out) {
    __shared__ __align__(8)  __half ws[CKK * TO];   // 2304 B, [ck][4ch]
    __shared__ __align__(16) __half2 xs[XS_SIZE];   // 22272 B, dup'd pairs

    const int tid   = threadIdx.x;
    const int og    = blockIdx.x;
    const int band  = blockIdx.y;
    const int b     = blockIdx.z;
    const int obase = og * TO;
    const int hbase = band * TH;

    // Weights: ws[ck*4 + oo] = half(w[(obase+oo)*CKK + ck])
    for (int i = tid; i < CKK * TO; i += THREADS) {
        int ck = i / TO;
        int oo = i % TO;
        ws[i] = __float2half(w[(obase + oo) * CKK + ck]);
    }

    const int row = tid / Wn;  // 0..3
    const int col = tid % Wn;  // 0..55

    float f0 = 0.f, f1 = 0.f, f2 = 0.f, f3 = 0.f;

    for (int ch = 0; ch < NCHUNK; ch++) {
        __syncthreads();
        // Stage 16 channels of x as duplicated half2, padded 6x58
        for (int i = tid; i < XS_SIZE; i += THREADS) {
            int cc  = i / XS_PLANE;
            int rem = i % XS_PLANE;
            int r   = rem / XS_COLS;
            int cl  = rem % XS_COLS;
            int gh  = hbase + r - 1;
            int gw  = cl - 1;
            float v = 0.f;
            if (gh >= 0 && gh < Hn && gw >= 0 && gw < Wn)
                v = x[((b * Cn + ch * CCHUNK + cc) * Hn + gh) * Wn + gw];
            xs[i] = __float2half2_rn(v);
        }
        __syncthreads();

#pragma unroll 4
        for (int cc = 0; cc < CCHUNK; cc++) {
            const __half2* xbase = &xs[cc * XS_PLANE + row * XS_COLS + col];
            __half2 xv[9];
#pragma unroll
            for (int kh = 0; kh < 3; kh++)
#pragma unroll
                for (int kw = 0; kw < 3; kw++)
                    xv[kh * 3 + kw] = xbase[kh * XS_COLS + kw];

            const uint2* wp = reinterpret_cast<const uint2*>(
                &ws[(ch * CCHUNK + cc) * KK * TO]);

            __half2 h01, h23;
            {
                uint2 wv = wp[0];   // LDS.64 broadcast: 4 weights
                h01 = __hmin2(xv[0], *reinterpret_cast<__half2*>(&wv.x));
                h23 = __hmin2(xv[0], *reinterpret_cast<__half2*>(&wv.y));
            }
#pragma unroll
            for (int p = 1; p < 9; p++) {
                uint2 wv = wp[p];
                h01 = __hadd2(h01, __hmin2(xv[p], *reinterpret_cast<__half2*>(&wv.x)));
                h23 = __hadd2(h23, __hmin2(xv[p], *reinterpret_cast<__half2*>(&wv.y)));
            }
            // flush 9-term fp16 chunk into fp32 accumulators
            f0 += __low2float(h01);  f1 += __high2float(h01);
            f2 += __low2float(h23);  f3 += __high2float(h23);
        }
    }

    const float mu = g_mu;
    const int h = hbase + row;
    float* dst = &out[((b * On + obase) * Hn + h) * Wn + col];
    dst[0 * Hn * Wn] = mu * f0;
    dst[1 * Hn * Wn] = mu * f1;
    dst[2 * Hn * Wn] = mu * f2;
    dst[3 * Hn * Wn] = mu * f3;
}

extern "C" void kernel_launch(void* const* d_in, const int* in_sizes, int n_in,
                              void* d_out, int out_size) {
    const float* x = (const float*)d_in[0];
    const float* w = (const float*)d_in[1];
    float* out = (float*)d_out;

    mu_kernel<<<1, 1024>>>(w);

    dim3 grid(OG, NBAND, Bn);
    approx_conv_kernel<<<grid, THREADS>>>(x, w, out);
}

// round 9
// speedup vs baseline: 1.2912x; 1.2912x over previous
#include <cuda_runtime.h>
#include <cuda_fp16.h>

// ApproximateConv2d: z[b,o,h,w] = mu_w * sum_{c,kh,kw} min(x_pad, w)
// x: (4,32,56,56) f32, w: (64,32,3,3) f32, out: (4,64,56,56) f32
//
// R9 = R7 fp16 inner math (TO=8, 1.53 slots/contrib) + in-block channel split:
// 448-thread blocks, two 224-thread halves each covering 16 input channels,
// partials combined through smem. 200K threads -> 42 warps/SM.

#define Bn 4
#define Cn 32
#define Hn 56
#define Wn 56
#define On 64
#define KK 9
#define CKK 288

#define TO 8               // output channels per thread
#define OG (On / TO)       // 8
#define TH 4               // output rows per block
#define NBAND (Hn / TH)    // 14
#define HALFT (TH * Wn)    // 224 threads per channel-half
#define THREADS (2 * HALFT) // 448

#define CHALF 16           // channels per half
#define LCK (CHALF * KK)   // 144
#define XS_ROWS (TH + 2)   // 6
#define XS_COLS (Wn + 2)   // 58
#define XS_PLANE (XS_ROWS * XS_COLS)    // 348
#define XS_SIZE (Cn * XS_PLANE)         // 11136 half2 = 44544 B

#define WS_BYTES (2 * LCK * TO * 2)     // 4608 B
#define SMEM_BYTES (XS_SIZE * 4 + WS_BYTES)  // 49152 B

__device__ float g_mu;

// ---------------------------------------------------------------------------
// mu_w = mean(|w|) in fp32 (exact)
// ---------------------------------------------------------------------------
__global__ __launch_bounds__(1024)
void mu_kernel(const float* __restrict__ w) {
    __shared__ float red[32];
    const int n4 = (On * CKK) / 4; // 4608
    const float4* w4 = reinterpret_cast<const float4*>(w);
    float s = 0.f;
    for (int i = threadIdx.x; i < n4; i += 1024) {
        float4 v = w4[i];
        s += fabsf(v.x) + fabsf(v.y) + fabsf(v.z) + fabsf(v.w);
    }
#pragma unroll
    for (int off = 16; off > 0; off >>= 1)
        s += __shfl_xor_sync(0xffffffffu, s, off);
    if ((threadIdx.x & 31) == 0) red[threadIdx.x >> 5] = s;
    __syncthreads();
    if (threadIdx.x < 32) {
        float t = red[threadIdx.x];
#pragma unroll
        for (int off = 16; off > 0; off >>= 1)
            t += __shfl_xor_sync(0xffffffffu, t, off);
        if (threadIdx.x == 0) g_mu = t / (float)(On * CKK);
    }
}

// ---------------------------------------------------------------------------
// Main kernel. grid = (8, 14, 4) = 448 blocks of 448 threads (3/SM).
// halves: tid/224 selects channel half; wtid = tid%224 = output pixel.
// ---------------------------------------------------------------------------
__global__ __launch_bounds__(THREADS, 3)
void approx_conv_kernel(const float* __restrict__ x,
                        const float* __restrict__ w,
                        float* __restrict__ out) {
    __shared__ __align__(16) unsigned char sraw[SMEM_BYTES];
    __half2* xs = reinterpret_cast<__half2*>(sraw);              // [32][348]
    __half*  ws = reinterpret_cast<__half*>(sraw + XS_SIZE * 4); // [2][144][8]
    float*   red = reinterpret_cast<float*>(sraw);               // aliases xs

    const int tid  = threadIdx.x;
    const int half = tid / HALFT;
    const int wtid = tid % HALFT;
    const int og    = blockIdx.x;
    const int band  = blockIdx.y;
    const int b     = blockIdx.z;
    const int obase = og * TO;
    const int hbase = band * TH;

    // Weights: ws[hf][lck][oo] = half(w[(obase+oo)*CKK + hf*LCK + lck])
    for (int i = tid; i < 2 * LCK * TO; i += THREADS) {
        int hf  = i / (LCK * TO);
        int r   = i % (LCK * TO);
        int lck = r / TO;
        int oo  = r % TO;
        ws[i] = __float2half(w[(obase + oo) * CKK + hf * LCK + lck]);
    }

    // Stage all 32 channels of x as duplicated half2, padded 6x58
    for (int i = tid; i < XS_SIZE; i += THREADS) {
        int cc  = i / XS_PLANE;
        int rem = i % XS_PLANE;
        int r   = rem / XS_COLS;
        int cl  = rem % XS_COLS;
        int gh  = hbase + r - 1;
        int gw  = cl - 1;
        float v = 0.f;
        if (gh >= 0 && gh < Hn && gw >= 0 && gw < Wn)
            v = x[((b * Cn + cc) * Hn + gh) * Wn + gw];
        xs[i] = __float2half2_rn(v);
    }
    __syncthreads();

    const int row = wtid / Wn;  // 0..3
    const int col = wtid % Wn;  // 0..55

    float f0 = 0.f, f1 = 0.f, f2 = 0.f, f3 = 0.f;
    float f4 = 0.f, f5 = 0.f, f6 = 0.f, f7 = 0.f;

    const __half* wsh = ws + half * (LCK * TO);
    const __half2* xh = xs + (half * CHALF) * XS_PLANE + row * XS_COLS + col;

#pragma unroll 2
    for (int cc = 0; cc < CHALF; cc++) {
        const __half2* xbase = xh + cc * XS_PLANE;
        __half2 xv[9];
#pragma unroll
        for (int kh = 0; kh < 3; kh++)
#pragma unroll
            for (int kw = 0; kw < 3; kw++)
                xv[kh * 3 + kw] = xbase[kh * XS_COLS + kw];

        const uint4* wp = reinterpret_cast<const uint4*>(wsh + cc * KK * TO);

        __half2 h0, h1, h2, h3;
        {
            uint4 wv = wp[0];   // LDS.128 broadcast: 8 weights
            h0 = __hmin2(xv[0], *reinterpret_cast<__half2*>(&wv.x));
            h1 = __hmin2(xv[0], *reinterpret_cast<__half2*>(&wv.y));
            h2 = __hmin2(xv[0], *reinterpret_cast<__half2*>(&wv.z));
            h3 = __hmin2(xv[0], *reinterpret_cast<__half2*>(&wv.w));
        }
#pragma unroll
        for (int p = 1; p < 9; p++) {
            uint4 wv = wp[p];
            h0 = __hadd2(h0, __hmin2(xv[p], *reinterpret_cast<__half2*>(&wv.x)));
            h1 = __hadd2(h1, __hmin2(xv[p], *reinterpret_cast<__half2*>(&wv.y)));
            h2 = __hadd2(h2, __hmin2(xv[p], *reinterpret_cast<__half2*>(&wv.z)));
            h3 = __hadd2(h3, __hmin2(xv[p], *reinterpret_cast<__half2*>(&wv.w)));
        }
        // flush 9-term fp16 chunk into fp32 accumulators
        f0 += __low2float(h0);  f1 += __high2float(h0);
        f2 += __low2float(h1);  f3 += __high2float(h1);
        f4 += __low2float(h2);  f5 += __high2float(h2);
        f6 += __low2float(h3);  f7 += __high2float(h3);
    }

    __syncthreads();  // xs reads complete; red may alias xs now

    if (half == 1) {
        red[0 * HALFT + wtid] = f0;
        red[1 * HALFT + wtid] = f1;
        red[2 * HALFT + wtid] = f2;
        red[3 * HALFT + wtid] = f3;
        red[4 * HALFT + wtid] = f4;
        red[5 * HALFT + wtid] = f5;
        red[6 * HALFT + wtid] = f6;
        red[7 * HALFT + wtid] = f7;
    }
    __syncthreads();

    if (half == 0) {
        const float mu = g_mu;
        const int h = hbase + row;
        float* dst = &out[((b * On + obase) * Hn + h) * Wn + col];
        dst[0 * Hn * Wn] = mu * (f0 + red[0 * HALFT + wtid]);
        dst[1 * Hn * Wn] = mu * (f1 + red[1 * HALFT + wtid]);
        dst[2 * Hn * Wn] = mu * (f2 + red[2 * HALFT + wtid]);
        dst[3 * Hn * Wn] = mu * (f3 + red[3 * HALFT + wtid]);
        dst[4 * Hn * Wn] = mu * (f4 + red[4 * HALFT + wtid]);
        dst[5 * Hn * Wn] = mu * (f5 + red[5 * HALFT + wtid]);
        dst[6 * Hn * Wn] = mu * (f6 + red[6 * HALFT + wtid]);
        dst[7 * Hn * Wn] = mu * (f7 + red[7 * HALFT + wtid]);
    }
}

extern "C" void kernel_launch(void* const* d_in, const int* in_sizes, int n_in,
                              void* d_out, int out_size) {
    const float* x = (const float*)d_in[0];
    const float* w = (const float*)d_in[1];
    float* out = (float*)d_out;

    mu_kernel<<<1, 1024>>>(w);

    dim3 grid(OG, NBAND, Bn);
    approx_conv_kernel<<<grid, THREADS>>>(x, w, out);
}